// round 12
// baseline (speedup 1.0000x reference)
#include <cuda_runtime.h>
#include <math.h>
#include <stdint.h>

#define NN   50000
#define EE   800000
#define NE2  850000      // EE + NN self loops
#define HIDD 128
#define NB   196         // ceil(NN/256) scan blocks

#define RBLK      128                         // GEMM M-tile
#define NRB       ((NN + RBLK - 1) / RBLK)    // 391 row blocks
#define NRB_A     196                         // first-half row blocks
#define NRB_B     (NRB - NRB_A)               // 195
#define SPLIT_N   (NRB_A * RBLK)              // 25088 node split
#define NODES_A   SPLIT_N
#define NODES_B   (NN - SPLIT_N)              // 24912

// ---------------- scratch (device globals; no runtime allocation) ----------------
__device__ float g_h  [(size_t)NN * HIDD];
__device__ float g_fs [(size_t)NN * HIDD];
__device__ float g_fd [(size_t)NN * HIDD];
__device__ int   g_csr_src[NE2];
__device__ int   g_rowptr [NN + 1];
__device__ int   g_cursor [NN];             // doubles as histogram counts
__device__ int   g_bsum[NB];

// ================= CSR build (per launch; dst-only, layer-invariant) =============
__global__ void k_zero_cnt(float* __restrict__ out)
{
    int i = blockIdx.x * blockDim.x + threadIdx.x;
    if (i < NN) g_cursor[i] = 0;
    if (i < HIDD) out[i] = 0.f;               // zero graph-mean accumulator
}

__global__ void k_hist(const int* __restrict__ dst)
{
    int e = blockIdx.x * blockDim.x + threadIdx.x;
    if (e >= NE2) return;
    int d = (e < EE) ? dst[e] : e - EE;
    atomicAdd(&g_cursor[d], 1);
}

__global__ void k_scan1()
{
    __shared__ int s[256];
    int t = threadIdx.x, i = blockIdx.x * 256 + t;
    int v = (i < NN) ? g_cursor[i] : 0;
    s[t] = v; __syncthreads();
    for (int o = 1; o < 256; o <<= 1) {
        int x = (t >= o) ? s[t - o] : 0;
        __syncthreads();
        s[t] += x;
        __syncthreads();
    }
    if (i < NN) g_rowptr[i] = s[t] - v;          // block-local exclusive
    if (t == 255) g_bsum[blockIdx.x] = s[255];
}

// scan3 with inlined block-offset reduction
__global__ void k_scan3()
{
    __shared__ int red[256];
    int t = threadIdx.x;
    int bid = blockIdx.x;
    int v = (t < NB && t < bid) ? g_bsum[t] : 0;
    red[t] = v; __syncthreads();
    #pragma unroll
    for (int o = 128; o; o >>= 1) {
        if (t < o) red[t] += red[t + o];
        __syncthreads();
    }
    int boff = red[0];
    int i = bid * 256 + t;
    if (i < NN) {
        int rp = g_rowptr[i] + boff;
        g_rowptr[i] = rp;
        g_cursor[i] = rp;                        // fill cursor
    }
    if (i == 0) g_rowptr[NN] = NE2;
}

__global__ void k_fill(const int* __restrict__ src, const int* __restrict__ dst)
{
    int e = blockIdx.x * blockDim.x + threadIdx.x;
    if (e >= NE2) return;
    int s, d;
    if (e < EE) { s = src[e]; d = dst[e]; } else { s = e - EE; d = s; }
    int pos = atomicAdd(&g_cursor[d], 1);
    g_csr_src[pos] = s;
}

// ===================== tf32 tensor-core GEMM machinery ===========================
__device__ __forceinline__ uint32_t f2tf(float x)   // round-to-nearest tf32
{
    uint32_t r;
    asm("cvt.rna.tf32.f32 %0, %1;" : "=r"(r) : "f"(x));
    return r;
}

__device__ __forceinline__ void mma_tf32(
    float& c0, float& c1, float& c2, float& c3,
    uint32_t a0, uint32_t a1, uint32_t a2, uint32_t a3,
    uint32_t b0, uint32_t b1)
{
    asm volatile(
        "mma.sync.aligned.m16n8k8.row.col.f32.tf32.tf32.f32 "
        "{%0,%1,%2,%3},{%4,%5,%6,%7},{%8,%9},{%0,%1,%2,%3};"
        : "+f"(c0), "+f"(c1), "+f"(c2), "+f"(c3)
        : "r"(a0), "r"(a1), "r"(a2), "r"(a3), "r"(b0), "r"(b1));
}

__device__ __forceinline__ void cp_async16(void* dst, const void* src, bool pred)
{
    uint32_t d = (uint32_t)__cvta_generic_to_shared(dst);
    int n = pred ? 16 : 0;
    asm volatile("cp.async.cg.shared.global [%0], [%1], 16, %2;"
                 :: "r"(d), "l"(src), "r"(n));
}
#define CP_COMMIT() asm volatile("cp.async.commit_group;")
#define CP_WAIT(N)  asm volatile("cp.async.wait_group %0;" :: "n"(N))

// smem layout (dynamic): As[2][128][36], Bs[2][32][132]
#define A_ST  (128 * 36)
#define B_ST  (32 * 132)
#define SMEM_BYTES ((2 * A_ST + 2 * B_ST) * 4)

template<int KTOT, int AROW>
__device__ __forceinline__ void gemm_tc_body(
    const float* __restrict__ A, const float* __restrict__ W,
    const float* __restrict__ bias, float* __restrict__ F, int rb0)
{
    extern __shared__ float sm[];
    float* AsB = sm;
    float* BsB = sm + 2 * A_ST;

    int tid = threadIdx.x;
    int lane = tid & 31, wid = tid >> 5;
    int wm = wid >> 2, wn = wid & 3;          // warp grid 2(m) x 4(n)
    int l4 = lane >> 2, lk = lane & 3;
    int row0 = (blockIdx.x + rb0) * RBLK;

    float c[4][4][4];
    #pragma unroll
    for (int i = 0; i < 4; i++)
        #pragma unroll
        for (int j = 0; j < 4; j++)
            #pragma unroll
            for (int q = 0; q < 4; q++) c[i][j][q] = 0.f;

    auto load_tiles = [&](int k0, int st) {
        float* As = AsB + st * A_ST;
        float* Bs = BsB + st * B_ST;
        #pragma unroll
        for (int i = 0; i < 4; i++) {
            int cix = tid + i * 256;
            int r = cix >> 3, cc = (cix & 7) * 4;
            int row = row0 + r;
            cp_async16(&As[r * 36 + cc], &A[(size_t)row * AROW + k0 + cc], row < NN);
        }
        #pragma unroll
        for (int i = 0; i < 4; i++) {
            int cix = tid + i * 256;
            int kk = cix >> 5, cc = (cix & 31) * 4;
            cp_async16(&Bs[kk * 132 + cc], &W[(size_t)(k0 + kk) * HIDD + cc], true);
        }
        CP_COMMIT();
    };

    const int NIT = KTOT / 32;
    load_tiles(0, 0);
    #pragma unroll
    for (int it = 0; it < NIT; it++) {
        int st = it & 1;
        if (it + 1 < NIT) { load_tiles((it + 1) * 32, st ^ 1); CP_WAIT(1); }
        else              { CP_WAIT(0); }
        __syncthreads();

        const float* As = AsB + st * A_ST;
        const float* Bs = BsB + st * B_ST;
        #pragma unroll
        for (int ks = 0; ks < 4; ks++) {
            int kc = ks * 8 + lk;
            uint32_t a[4][4], b[4][2];
            #pragma unroll
            for (int mf = 0; mf < 4; mf++) {
                int m0 = wm * 64 + mf * 16;
                a[mf][0] = f2tf(As[(m0 + l4    ) * 36 + kc    ]);
                a[mf][1] = f2tf(As[(m0 + l4 + 8) * 36 + kc    ]);
                a[mf][2] = f2tf(As[(m0 + l4    ) * 36 + kc + 4]);
                a[mf][3] = f2tf(As[(m0 + l4 + 8) * 36 + kc + 4]);
            }
            #pragma unroll
            for (int nf = 0; nf < 4; nf++) {
                int n0 = wn * 32 + nf * 8 + l4;
                b[nf][0] = f2tf(Bs[(ks * 8 + lk    ) * 132 + n0]);
                b[nf][1] = f2tf(Bs[(ks * 8 + lk + 4) * 132 + n0]);
            }
            #pragma unroll
            for (int mf = 0; mf < 4; mf++)
                #pragma unroll
                for (int nf = 0; nf < 4; nf++)
                    mma_tf32(c[mf][nf][0], c[mf][nf][1], c[mf][nf][2], c[mf][nf][3],
                             a[mf][0], a[mf][1], a[mf][2], a[mf][3],
                             b[nf][0], b[nf][1]);
        }
        __syncthreads();
    }

    // epilogue: bias + store
    #pragma unroll
    for (int mf = 0; mf < 4; mf++) {
        int r = row0 + wm * 64 + mf * 16 + l4;
        #pragma unroll
        for (int nf = 0; nf < 4; nf++) {
            int col = wn * 32 + nf * 8 + lk * 2;
            float2 bb = *(const float2*)&bias[col];
            if (r < NN) {
                float2 o = { c[mf][nf][0] + bb.x, c[mf][nf][1] + bb.y };
                *(float2*)&F[(size_t)r * HIDD + col] = o;
            }
            if (r + 8 < NN) {
                float2 o = { c[mf][nf][2] + bb.x, c[mf][nf][3] + bb.y };
                *(float2*)&F[(size_t)(r + 8) * HIDD + col] = o;
            }
        }
    }
}

__global__ __launch_bounds__(256) void k_gemm_in_tc(
    const float* __restrict__ A,     // [NN,64]
    const float* __restrict__ W,     // [64,128]
    const float* __restrict__ bias)
{
    gemm_tc_body<64, 64>(A, W, bias, g_h, 0);
}

__global__ __launch_bounds__(256) void k_gemm_dual_tc(
    const float* __restrict__ Ws, const float* __restrict__ bs,
    const float* __restrict__ Wd, const float* __restrict__ bd,
    int rb0)
{
    if (blockIdx.y) gemm_tc_body<128, 128>(g_h, Wd, bd, g_fd, rb0);
    else            gemm_tc_body<128, 128>(g_h, Ws, bs, g_fs, rb0);
}

// ====== fused single-pass attention + aggregation + residual + LN + ReLU =========
// 2-edge unrolled. Processes nodes [n0, n0+cnt).
__global__ __launch_bounds__(256) void k_agg_ln(
    const float* __restrict__ attn,   // [4*32] this layer
    const float* __restrict__ lng, const float* __restrict__ lnb,
    float* __restrict__ outh,         // last-layer copy target or null
    int n0, int cnt)
{
    int n = (int)((blockIdx.x * 256 + threadIdx.x) >> 5);
    int lane = threadIdx.x & 31;
    if (n >= cnt) return;
    n += n0;

    float4 fdv = *(const float4*)(g_fd + (size_t)n * HIDD + lane * 4);
    float4 wa  = *(const float4*)(attn + lane * 4);

    int beg = g_rowptr[n], end = g_rowptr[n + 1];

    float z = 0.f;
    float m0 = 0.f, m1 = 0.f, m2 = 0.f, m3 = 0.f;

    int i = beg;
    if ((end - beg) & 1) {
        int s = g_csr_src[i]; i++;
        float4 a = *(const float4*)(g_fs + (size_t)s * HIDD + lane * 4);
        float x0 = a.x + fdv.x; x0 = x0 > 0.f ? x0 : 0.2f * x0;
        float x1 = a.y + fdv.y; x1 = x1 > 0.f ? x1 : 0.2f * x1;
        float x2 = a.z + fdv.z; x2 = x2 > 0.f ? x2 : 0.2f * x2;
        float x3 = a.w + fdv.w; x3 = x3 > 0.f ? x3 : 0.2f * x3;
        float lg = x0 * wa.x + x1 * wa.y + x2 * wa.z + x3 * wa.w;
        lg += __shfl_xor_sync(0xffffffffu, lg, 4);
        lg += __shfl_xor_sync(0xffffffffu, lg, 2);
        lg += __shfl_xor_sync(0xffffffffu, lg, 1);
        float p = __expf(lg);
        z += p;
        m0 += p * a.x; m1 += p * a.y; m2 += p * a.z; m3 += p * a.w;
    }
    for (; i < end; i += 2) {
        int s0 = g_csr_src[i];
        int s1 = g_csr_src[i + 1];
        float4 a0 = *(const float4*)(g_fs + (size_t)s0 * HIDD + lane * 4);
        float4 a1 = *(const float4*)(g_fs + (size_t)s1 * HIDD + lane * 4);

        float u0 = a0.x + fdv.x; u0 = u0 > 0.f ? u0 : 0.2f * u0;
        float u1 = a0.y + fdv.y; u1 = u1 > 0.f ? u1 : 0.2f * u1;
        float u2 = a0.z + fdv.z; u2 = u2 > 0.f ? u2 : 0.2f * u2;
        float u3 = a0.w + fdv.w; u3 = u3 > 0.f ? u3 : 0.2f * u3;
        float v0 = a1.x + fdv.x; v0 = v0 > 0.f ? v0 : 0.2f * v0;
        float v1 = a1.y + fdv.y; v1 = v1 > 0.f ? v1 : 0.2f * v1;
        float v2 = a1.z + fdv.z; v2 = v2 > 0.f ? v2 : 0.2f * v2;
        float v3 = a1.w + fdv.w; v3 = v3 > 0.f ? v3 : 0.2f * v3;

        float lgA = u0 * wa.x + u1 * wa.y + u2 * wa.z + u3 * wa.w;
        float lgB = v0 * wa.x + v1 * wa.y + v2 * wa.z + v3 * wa.w;
        lgA += __shfl_xor_sync(0xffffffffu, lgA, 4);
        lgB += __shfl_xor_sync(0xffffffffu, lgB, 4);
        lgA += __shfl_xor_sync(0xffffffffu, lgA, 2);
        lgB += __shfl_xor_sync(0xffffffffu, lgB, 2);
        lgA += __shfl_xor_sync(0xffffffffu, lgA, 1);
        lgB += __shfl_xor_sync(0xffffffffu, lgB, 1);

        float pA = __expf(lgA);
        float pB = __expf(lgB);
        z += pA + pB;
        m0 += pA * a0.x + pB * a1.x;
        m1 += pA * a0.y + pB * a1.y;
        m2 += pA * a0.z + pB * a1.z;
        m3 += pA * a0.w + pB * a1.w;
    }
    float inv_z = 1.f / z;
    m0 *= inv_z; m1 *= inv_z; m2 *= inv_z; m3 *= inv_z;

    // residual + LN + ReLU
    size_t base = (size_t)n * HIDD + lane * 4;
    float4 hv = *(const float4*)(g_h + base);
    float x0 = 2.f * hv.x + m0;
    float x1 = 2.f * hv.y + m1;
    float x2 = 2.f * hv.z + m2;
    float x3 = 2.f * hv.w + m3;
    float su = x0 + x1 + x2 + x3;
    #pragma unroll
    for (int o = 16; o; o >>= 1) su += __shfl_xor_sync(0xffffffffu, su, o);
    float mu = su * (1.f / 128.f);
    float d0 = x0 - mu, d1 = x1 - mu, d2 = x2 - mu, d3 = x3 - mu;
    float sv = d0 * d0 + d1 * d1 + d2 * d2 + d3 * d3;
    #pragma unroll
    for (int o = 16; o; o >>= 1) sv += __shfl_xor_sync(0xffffffffu, sv, o);
    float inv = rsqrtf(sv * (1.f / 128.f) + 1e-5f);
    float4 gg = *(const float4*)(lng + lane * 4);
    float4 bb = *(const float4*)(lnb + lane * 4);
    float y0 = fmaxf(d0 * inv * gg.x + bb.x, 0.f);
    float y1 = fmaxf(d1 * inv * gg.y + bb.y, 0.f);
    float y2 = fmaxf(d2 * inv * gg.z + bb.z, 0.f);
    float y3 = fmaxf(d3 * inv * gg.w + bb.w, 0.f);
    float4 y = { y0, y1, y2, y3 };
    *(float4*)(g_h + base) = y;
    if (outh) *(float4*)(outh + base) = y;
}

// ---------------- graph mean ----------------
__global__ void k_mean(float* __restrict__ out)
{
    int c = threadIdx.x;              // 128 threads = feature
    int chunk = (NN + gridDim.x - 1) / gridDim.x;
    int n0 = blockIdx.x * chunk;
    int n1 = n0 + chunk; if (n1 > NN) n1 = NN;
    float s = 0.f;
    for (int n = n0; n < n1; n++) s += g_h[(size_t)n * HIDD + c];
    atomicAdd(&out[c], s * (1.f / (float)NN));
}

// ---------------- launch ----------------
extern "C" void kernel_launch(void* const* d_in, const int* in_sizes, int n_in,
                              void* d_out, int out_size)
{
    const float* nf    = (const float*)d_in[0];
    const int*   src   = (const int*)  d_in[1];
    const int*   dst   = (const int*)  d_in[2];
    const float* W_in  = (const float*)d_in[3];
    const float* b_in  = (const float*)d_in[4];
    const float* W_src = (const float*)d_in[5];
    const float* b_src = (const float*)d_in[6];
    const float* W_dst = (const float*)d_in[7];
    const float* b_dst = (const float*)d_in[8];
    const float* attn  = (const float*)d_in[9];
    const float* ln_g  = (const float*)d_in[10];
    const float* ln_b  = (const float*)d_in[11];
    float* out = (float*)d_out;

    (void)in_sizes; (void)n_in; (void)out_size;

    // lazily-created side stream + events (host-side resources only; the work
    // performed per call is identical every time)
    static cudaStream_t s2 = nullptr;
    static cudaEvent_t evF, evCSR, evA0, evA1, evG0, evG1;
    if (!s2) {
        cudaStreamCreateWithFlags(&s2, cudaStreamNonBlocking);
        cudaEventCreateWithFlags(&evF,   cudaEventDisableTiming);
        cudaEventCreateWithFlags(&evCSR, cudaEventDisableTiming);
        cudaEventCreateWithFlags(&evA0,  cudaEventDisableTiming);
        cudaEventCreateWithFlags(&evA1,  cudaEventDisableTiming);
        cudaEventCreateWithFlags(&evG0,  cudaEventDisableTiming);
        cudaEventCreateWithFlags(&evG1,  cudaEventDisableTiming);
    }

    cudaFuncSetAttribute(k_gemm_in_tc,
        cudaFuncAttributeMaxDynamicSharedMemorySize, SMEM_BYTES);
    cudaFuncSetAttribute(k_gemm_dual_tc,
        cudaFuncAttributeMaxDynamicSharedMemorySize, SMEM_BYTES);

    const int gE = (NE2 + 255) / 256;
    const int gN = (NN + 255) / 256;
    const int gAggA = (NODES_A * 32 + 255) / 256;
    const int gAggB = (NODES_B * 32 + 255) / 256;

    // ---- fork: CSR build on s2, overlapped with gemm_in + layer-0 dual GEMM ----
    cudaEventRecord(evF, 0);
    cudaStreamWaitEvent(s2, evF, 0);
    k_zero_cnt<<<gN, 256, 0, s2>>>(out);
    k_hist<<<gE, 256, 0, s2>>>(dst);
    k_scan1<<<NB, 256, 0, s2>>>();
    k_scan3<<<gN, 256, 0, s2>>>();
    k_fill<<<gE, 256, 0, s2>>>(src, dst);
    cudaEventRecord(evCSR, s2);

    // ---- main stream: input projection + layer-0 dual GEMM (full grid) ----
    k_gemm_in_tc<<<NRB, 256, SMEM_BYTES>>>(nf, W_in, b_in);
    k_gemm_dual_tc<<<dim3(NRB, 2), 256, SMEM_BYTES>>>(
        W_src, b_src, W_dst, b_dst, 0);
    cudaStreamWaitEvent(0, evCSR, 0);          // CSR ready before first agg

    cudaEvent_t evAs[2] = { evA0, evA1 };
    cudaEvent_t evGs[2] = { evG0, evG1 };

    for (int l = 0; l < 3; l++) {
        const float* at = attn + (size_t)l * HIDD;
        const float* lg = ln_g + (size_t)l * HIDD;
        const float* lb = ln_b + (size_t)l * HIDD;
        float* oh = (l == 2) ? (out + HIDD) : nullptr;

        // agg half A (nodes [0, SPLIT_N))
        k_agg_ln<<<gAggA, 256>>>(at, lg, lb, oh, 0, NODES_A);
        if (l < 2) cudaEventRecord(evAs[l], 0);
        // agg half B (nodes [SPLIT_N, NN))
        k_agg_ln<<<gAggB, 256>>>(at, lg, lb, oh, SPLIT_N, NODES_B);

        if (l < 2) {
            const float* Ws = W_src + (size_t)(l + 1) * HIDD * HIDD;
            const float* bs = b_src + (size_t)(l + 1) * HIDD;
            const float* Wd = W_dst + (size_t)(l + 1) * HIDD * HIDD;
            const float* bd = b_dst + (size_t)(l + 1) * HIDD;
            // next-layer GEMM half A on s2, overlapped with agg half B
            cudaStreamWaitEvent(s2, evAs[l], 0);
            k_gemm_dual_tc<<<dim3(NRB_A, 2), 256, SMEM_BYTES, s2>>>(
                Ws, bs, Wd, bd, 0);
            cudaEventRecord(evGs[l], s2);
            // next-layer GEMM half B on main stream (after agg half B)
            k_gemm_dual_tc<<<dim3(NRB_B, 2), 256, SMEM_BYTES>>>(
                Ws, bs, Wd, bd, NRB_A);
            cudaStreamWaitEvent(0, evGs[l], 0);  // join before next agg
        }
    }

    k_mean<<<500, 128>>>(out);
}

// round 13
// speedup vs baseline: 1.0172x; 1.0172x over previous
#include <cuda_runtime.h>
#include <math.h>
#include <stdint.h>

#define NN   50000
#define EE   800000
#define NE2  850000      // EE + NN self loops
#define HIDD 128
#define NB   196         // ceil(NN/256) scan blocks

#define RBLK  128                             // GEMM M-tile
#define NRB   ((NN + RBLK - 1) / RBLK)        // 391 row blocks

// ---------------- scratch (device globals; no runtime allocation) ----------------
__device__ float g_h  [(size_t)NN * HIDD];
__device__ float g_fs [(size_t)NN * HIDD];
__device__ float g_fd [(size_t)NN * HIDD];
__device__ int   g_csr_src[NE2];
__device__ int   g_rank[NE2];               // edge rank within its dst segment
__device__ int   g_rowptr [NN + 1];
__device__ int   g_cursor [NN];             // histogram counts
__device__ int   g_bsum[NB];

// ================= CSR build (per launch; dst-only, layer-invariant) =============
__global__ void k_zero_cnt(float* __restrict__ out)
{
    int i = blockIdx.x * blockDim.x + threadIdx.x;
    if (i < NN) g_cursor[i] = 0;
    if (i < HIDD) out[i] = 0.f;               // zero graph-mean accumulator
}

// histogram; atomicAdd return value = rank of this edge within its dst segment
__global__ void k_hist(const int* __restrict__ dst)
{
    int e = blockIdx.x * blockDim.x + threadIdx.x;
    if (e >= NE2) return;
    int d = (e < EE) ? dst[e] : e - EE;
    g_rank[e] = atomicAdd(&g_cursor[d], 1);
}

__global__ void k_scan1()
{
    __shared__ int s[256];
    int t = threadIdx.x, i = blockIdx.x * 256 + t;
    int v = (i < NN) ? g_cursor[i] : 0;
    s[t] = v; __syncthreads();
    for (int o = 1; o < 256; o <<= 1) {
        int x = (t >= o) ? s[t - o] : 0;
        __syncthreads();
        s[t] += x;
        __syncthreads();
    }
    if (i < NN) g_rowptr[i] = s[t] - v;          // block-local exclusive
    if (t == 255) g_bsum[blockIdx.x] = s[255];
}

// scan3 with inlined block-offset reduction
__global__ void k_scan3()
{
    __shared__ int red[256];
    int t = threadIdx.x;
    int bid = blockIdx.x;
    int v = (t < NB && t < bid) ? g_bsum[t] : 0;
    red[t] = v; __syncthreads();
    #pragma unroll
    for (int o = 128; o; o >>= 1) {
        if (t < o) red[t] += red[t + o];
        __syncthreads();
    }
    int boff = red[0];
    int i = bid * 256 + t;
    if (i < NN) g_rowptr[i] += boff;
    if (i == 0) g_rowptr[NN] = NE2;
}

// atomic-free fill: pos = rowptr[d] + rank[e]
__global__ void k_fill(const int* __restrict__ src, const int* __restrict__ dst)
{
    int e = blockIdx.x * blockDim.x + threadIdx.x;
    if (e >= NE2) return;
    int s, d;
    if (e < EE) { s = src[e]; d = dst[e]; } else { s = e - EE; d = s; }
    g_csr_src[g_rowptr[d] + g_rank[e]] = s;
}

// ===================== tf32 tensor-core GEMM machinery ===========================
__device__ __forceinline__ uint32_t f2tf(float x)   // round-to-nearest tf32
{
    uint32_t r;
    asm("cvt.rna.tf32.f32 %0, %1;" : "=r"(r) : "f"(x));
    return r;
}

__device__ __forceinline__ void mma_tf32(
    float& c0, float& c1, float& c2, float& c3,
    uint32_t a0, uint32_t a1, uint32_t a2, uint32_t a3,
    uint32_t b0, uint32_t b1)
{
    asm volatile(
        "mma.sync.aligned.m16n8k8.row.col.f32.tf32.tf32.f32 "
        "{%0,%1,%2,%3},{%4,%5,%6,%7},{%8,%9},{%0,%1,%2,%3};"
        : "+f"(c0), "+f"(c1), "+f"(c2), "+f"(c3)
        : "r"(a0), "r"(a1), "r"(a2), "r"(a3), "r"(b0), "r"(b1));
}

__device__ __forceinline__ void cp_async16(void* dst, const void* src, bool pred)
{
    uint32_t d = (uint32_t)__cvta_generic_to_shared(dst);
    int n = pred ? 16 : 0;
    asm volatile("cp.async.cg.shared.global [%0], [%1], 16, %2;"
                 :: "r"(d), "l"(src), "r"(n));
}
#define CP_COMMIT() asm volatile("cp.async.commit_group;")
#define CP_WAIT(N)  asm volatile("cp.async.wait_group %0;" :: "n"(N))

// smem layout (dynamic): As[2][128][36], Bs[2][32][132]
#define A_ST  (128 * 36)
#define B_ST  (32 * 132)
#define SMEM_BYTES ((2 * A_ST + 2 * B_ST) * 4)

template<int KTOT, int AROW>
__device__ __forceinline__ void gemm_tc_body(
    const float* __restrict__ A, const float* __restrict__ W,
    const float* __restrict__ bias, float* __restrict__ F)
{
    extern __shared__ float sm[];
    float* AsB = sm;
    float* BsB = sm + 2 * A_ST;

    int tid = threadIdx.x;
    int lane = tid & 31, wid = tid >> 5;
    int wm = wid >> 2, wn = wid & 3;          // warp grid 2(m) x 4(n)
    int l4 = lane >> 2, lk = lane & 3;
    int row0 = blockIdx.x * RBLK;

    float c[4][4][4];
    #pragma unroll
    for (int i = 0; i < 4; i++)
        #pragma unroll
        for (int j = 0; j < 4; j++)
            #pragma unroll
            for (int q = 0; q < 4; q++) c[i][j][q] = 0.f;

    auto load_tiles = [&](int k0, int st) {
        float* As = AsB + st * A_ST;
        float* Bs = BsB + st * B_ST;
        #pragma unroll
        for (int i = 0; i < 4; i++) {
            int cix = tid + i * 256;
            int r = cix >> 3, cc = (cix & 7) * 4;
            int row = row0 + r;
            cp_async16(&As[r * 36 + cc], &A[(size_t)row * AROW + k0 + cc], row < NN);
        }
        #pragma unroll
        for (int i = 0; i < 4; i++) {
            int cix = tid + i * 256;
            int kk = cix >> 5, cc = (cix & 31) * 4;
            cp_async16(&Bs[kk * 132 + cc], &W[(size_t)(k0 + kk) * HIDD + cc], true);
        }
        CP_COMMIT();
    };

    const int NIT = KTOT / 32;
    load_tiles(0, 0);
    #pragma unroll
    for (int it = 0; it < NIT; it++) {
        int st = it & 1;
        if (it + 1 < NIT) { load_tiles((it + 1) * 32, st ^ 1); CP_WAIT(1); }
        else              { CP_WAIT(0); }
        __syncthreads();

        const float* As = AsB + st * A_ST;
        const float* Bs = BsB + st * B_ST;
        #pragma unroll
        for (int ks = 0; ks < 4; ks++) {
            int kc = ks * 8 + lk;
            uint32_t a[4][4], b[4][2];
            #pragma unroll
            for (int mf = 0; mf < 4; mf++) {
                int m0 = wm * 64 + mf * 16;
                a[mf][0] = f2tf(As[(m0 + l4    ) * 36 + kc    ]);
                a[mf][1] = f2tf(As[(m0 + l4 + 8) * 36 + kc    ]);
                a[mf][2] = f2tf(As[(m0 + l4    ) * 36 + kc + 4]);
                a[mf][3] = f2tf(As[(m0 + l4 + 8) * 36 + kc + 4]);
            }
            #pragma unroll
            for (int nf = 0; nf < 4; nf++) {
                int n0 = wn * 32 + nf * 8 + l4;
                b[nf][0] = f2tf(Bs[(ks * 8 + lk    ) * 132 + n0]);
                b[nf][1] = f2tf(Bs[(ks * 8 + lk + 4) * 132 + n0]);
            }
            #pragma unroll
            for (int mf = 0; mf < 4; mf++)
                #pragma unroll
                for (int nf = 0; nf < 4; nf++)
                    mma_tf32(c[mf][nf][0], c[mf][nf][1], c[mf][nf][2], c[mf][nf][3],
                             a[mf][0], a[mf][1], a[mf][2], a[mf][3],
                             b[nf][0], b[nf][1]);
        }
        __syncthreads();
    }

    // epilogue: bias + store
    #pragma unroll
    for (int mf = 0; mf < 4; mf++) {
        int r = row0 + wm * 64 + mf * 16 + l4;
        #pragma unroll
        for (int nf = 0; nf < 4; nf++) {
            int col = wn * 32 + nf * 8 + lk * 2;
            float2 bb = *(const float2*)&bias[col];
            if (r < NN) {
                float2 o = { c[mf][nf][0] + bb.x, c[mf][nf][1] + bb.y };
                *(float2*)&F[(size_t)r * HIDD + col] = o;
            }
            if (r + 8 < NN) {
                float2 o = { c[mf][nf][2] + bb.x, c[mf][nf][3] + bb.y };
                *(float2*)&F[(size_t)(r + 8) * HIDD + col] = o;
            }
        }
    }
}

__global__ __launch_bounds__(256) void k_gemm_in_tc(
    const float* __restrict__ A,     // [NN,64]
    const float* __restrict__ W,     // [64,128]
    const float* __restrict__ bias)
{
    gemm_tc_body<64, 64>(A, W, bias, g_h);
}

__global__ __launch_bounds__(256) void k_gemm_dual_tc(
    const float* __restrict__ Ws, const float* __restrict__ bs,
    const float* __restrict__ Wd, const float* __restrict__ bd)
{
    if (blockIdx.y) gemm_tc_body<128, 128>(g_h, Wd, bd, g_fd);
    else            gemm_tc_body<128, 128>(g_h, Ws, bs, g_fs);
}

// ====== fused single-pass attention + aggregation + residual + LN + ReLU =========
// 2-edge unrolled: two independent gather/logit/exp chains interleaved for ILP.
__global__ __launch_bounds__(256) void k_agg_ln(
    const float* __restrict__ attn,   // [4*32] this layer
    const float* __restrict__ lng, const float* __restrict__ lnb,
    float* __restrict__ outh)         // last-layer copy target or null
{
    int n = (blockIdx.x * 256 + threadIdx.x) >> 5;
    int lane = threadIdx.x & 31;
    if (n >= NN) return;

    float4 fdv = *(const float4*)(g_fd + (size_t)n * HIDD + lane * 4);
    float4 wa  = *(const float4*)(attn + lane * 4);

    int beg = g_rowptr[n], end = g_rowptr[n + 1];

    float z = 0.f;
    float m0 = 0.f, m1 = 0.f, m2 = 0.f, m3 = 0.f;

    int i = beg;
    if ((end - beg) & 1) {
        int s = g_csr_src[i]; i++;
        float4 a = *(const float4*)(g_fs + (size_t)s * HIDD + lane * 4);
        float x0 = a.x + fdv.x; x0 = x0 > 0.f ? x0 : 0.2f * x0;
        float x1 = a.y + fdv.y; x1 = x1 > 0.f ? x1 : 0.2f * x1;
        float x2 = a.z + fdv.z; x2 = x2 > 0.f ? x2 : 0.2f * x2;
        float x3 = a.w + fdv.w; x3 = x3 > 0.f ? x3 : 0.2f * x3;
        float lg = x0 * wa.x + x1 * wa.y + x2 * wa.z + x3 * wa.w;
        lg += __shfl_xor_sync(0xffffffffu, lg, 4);
        lg += __shfl_xor_sync(0xffffffffu, lg, 2);
        lg += __shfl_xor_sync(0xffffffffu, lg, 1);
        float p = __expf(lg);
        z += p;
        m0 += p * a.x; m1 += p * a.y; m2 += p * a.z; m3 += p * a.w;
    }
    for (; i < end; i += 2) {
        int s0 = g_csr_src[i];
        int s1 = g_csr_src[i + 1];
        float4 a0 = *(const float4*)(g_fs + (size_t)s0 * HIDD + lane * 4);
        float4 a1 = *(const float4*)(g_fs + (size_t)s1 * HIDD + lane * 4);

        float u0 = a0.x + fdv.x; u0 = u0 > 0.f ? u0 : 0.2f * u0;
        float u1 = a0.y + fdv.y; u1 = u1 > 0.f ? u1 : 0.2f * u1;
        float u2 = a0.z + fdv.z; u2 = u2 > 0.f ? u2 : 0.2f * u2;
        float u3 = a0.w + fdv.w; u3 = u3 > 0.f ? u3 : 0.2f * u3;
        float v0 = a1.x + fdv.x; v0 = v0 > 0.f ? v0 : 0.2f * v0;
        float v1 = a1.y + fdv.y; v1 = v1 > 0.f ? v1 : 0.2f * v1;
        float v2 = a1.z + fdv.z; v2 = v2 > 0.f ? v2 : 0.2f * v2;
        float v3 = a1.w + fdv.w; v3 = v3 > 0.f ? v3 : 0.2f * v3;

        float lgA = u0 * wa.x + u1 * wa.y + u2 * wa.z + u3 * wa.w;
        float lgB = v0 * wa.x + v1 * wa.y + v2 * wa.z + v3 * wa.w;
        lgA += __shfl_xor_sync(0xffffffffu, lgA, 4);
        lgB += __shfl_xor_sync(0xffffffffu, lgB, 4);
        lgA += __shfl_xor_sync(0xffffffffu, lgA, 2);
        lgB += __shfl_xor_sync(0xffffffffu, lgB, 2);
        lgA += __shfl_xor_sync(0xffffffffu, lgA, 1);
        lgB += __shfl_xor_sync(0xffffffffu, lgB, 1);

        float pA = __expf(lgA);
        float pB = __expf(lgB);
        z += pA + pB;
        m0 += pA * a0.x + pB * a1.x;
        m1 += pA * a0.y + pB * a1.y;
        m2 += pA * a0.z + pB * a1.z;
        m3 += pA * a0.w + pB * a1.w;
    }
    float inv_z = 1.f / z;
    m0 *= inv_z; m1 *= inv_z; m2 *= inv_z; m3 *= inv_z;

    // residual + LN + ReLU
    size_t base = (size_t)n * HIDD + lane * 4;
    float4 hv = *(const float4*)(g_h + base);
    float x0 = 2.f * hv.x + m0;
    float x1 = 2.f * hv.y + m1;
    float x2 = 2.f * hv.z + m2;
    float x3 = 2.f * hv.w + m3;
    float su = x0 + x1 + x2 + x3;
    #pragma unroll
    for (int o = 16; o; o >>= 1) su += __shfl_xor_sync(0xffffffffu, su, o);
    float mu = su * (1.f / 128.f);
    float d0 = x0 - mu, d1 = x1 - mu, d2 = x2 - mu, d3 = x3 - mu;
    float sv = d0 * d0 + d1 * d1 + d2 * d2 + d3 * d3;
    #pragma unroll
    for (int o = 16; o; o >>= 1) sv += __shfl_xor_sync(0xffffffffu, sv, o);
    float inv = rsqrtf(sv * (1.f / 128.f) + 1e-5f);
    float4 gg = *(const float4*)(lng + lane * 4);
    float4 bb = *(const float4*)(lnb + lane * 4);
    float y0 = fmaxf(d0 * inv * gg.x + bb.x, 0.f);
    float y1 = fmaxf(d1 * inv * gg.y + bb.y, 0.f);
    float y2 = fmaxf(d2 * inv * gg.z + bb.z, 0.f);
    float y3 = fmaxf(d3 * inv * gg.w + bb.w, 0.f);
    float4 y = { y0, y1, y2, y3 };
    *(float4*)(g_h + base) = y;
    if (outh) *(float4*)(outh + base) = y;
}

// ---------------- graph mean ----------------
__global__ void k_mean(float* __restrict__ out)
{
    int c = threadIdx.x;              // 128 threads = feature
    int chunk = (NN + gridDim.x - 1) / gridDim.x;
    int n0 = blockIdx.x * chunk;
    int n1 = n0 + chunk; if (n1 > NN) n1 = NN;
    float s = 0.f;
    for (int n = n0; n < n1; n++) s += g_h[(size_t)n * HIDD + c];
    atomicAdd(&out[c], s * (1.f / (float)NN));
}

// ---------------- launch ----------------
extern "C" void kernel_launch(void* const* d_in, const int* in_sizes, int n_in,
                              void* d_out, int out_size)
{
    const float* nf    = (const float*)d_in[0];
    const int*   src   = (const int*)  d_in[1];
    const int*   dst   = (const int*)  d_in[2];
    const float* W_in  = (const float*)d_in[3];
    const float* b_in  = (const float*)d_in[4];
    const float* W_src = (const float*)d_in[5];
    const float* b_src = (const float*)d_in[6];
    const float* W_dst = (const float*)d_in[7];
    const float* b_dst = (const float*)d_in[8];
    const float* attn  = (const float*)d_in[9];
    const float* ln_g  = (const float*)d_in[10];
    const float* ln_b  = (const float*)d_in[11];
    float* out = (float*)d_out;

    (void)in_sizes; (void)n_in; (void)out_size;

    // lazily-created side stream + events (host-side resources only)
    static cudaStream_t s2 = nullptr;
    static cudaEvent_t evF, evCSR;
    if (!s2) {
        cudaStreamCreateWithFlags(&s2, cudaStreamNonBlocking);
        cudaEventCreateWithFlags(&evF,   cudaEventDisableTiming);
        cudaEventCreateWithFlags(&evCSR, cudaEventDisableTiming);
    }

    cudaFuncSetAttribute(k_gemm_in_tc,
        cudaFuncAttributeMaxDynamicSharedMemorySize, SMEM_BYTES);
    cudaFuncSetAttribute(k_gemm_dual_tc,
        cudaFuncAttributeMaxDynamicSharedMemorySize, SMEM_BYTES);

    const int gE = (NE2 + 255) / 256;
    const int gN = (NN + 255) / 256;
    const int gNodeWarp = (NN * 32 + 255) / 256;

    // ---- fork: CSR build on s2, overlapped with gemm_in + layer-0 dual GEMM ----
    cudaEventRecord(evF, 0);
    cudaStreamWaitEvent(s2, evF, 0);
    k_zero_cnt<<<gN, 256, 0, s2>>>(out);
    k_hist<<<gE, 256, 0, s2>>>(dst);
    k_scan1<<<NB, 256, 0, s2>>>();
    k_scan3<<<gN, 256, 0, s2>>>();
    k_fill<<<gE, 256, 0, s2>>>(src, dst);
    cudaEventRecord(evCSR, s2);

    // ---- main stream: input projection + layer-0 dual GEMM ----
    k_gemm_in_tc<<<NRB, 256, SMEM_BYTES>>>(nf, W_in, b_in);
    k_gemm_dual_tc<<<dim3(NRB, 2), 256, SMEM_BYTES>>>(
        W_src, b_src, W_dst, b_dst);
    cudaStreamWaitEvent(0, evCSR, 0);          // CSR ready before first agg

    for (int l = 0; l < 3; l++) {
        k_agg_ln<<<gNodeWarp, 256>>>(
            attn + (size_t)l * HIDD,
            ln_g + (size_t)l * HIDD, ln_b + (size_t)l * HIDD,
            (l == 2) ? (out + HIDD) : nullptr);
        if (l < 2) {
            k_gemm_dual_tc<<<dim3(NRB, 2), 256, SMEM_BYTES>>>(
                W_src + (size_t)(l + 1) * HIDD * HIDD, b_src + (size_t)(l + 1) * HIDD,
                W_dst + (size_t)(l + 1) * HIDD * HIDD, b_dst + (size_t)(l + 1) * HIDD);
        }
    }

    k_mean<<<500, 128>>>(out);
}

// round 14
// speedup vs baseline: 1.0303x; 1.0129x over previous
#include <cuda_runtime.h>
#include <math.h>
#include <stdint.h>

#define NN   50000
#define EE   800000
#define NE2  850000      // EE + NN self loops
#define HIDD 128
#define NB   196         // ceil(NN/256) scan blocks

#define RBLK  128                             // GEMM M-tile
#define NRB   ((NN + RBLK - 1) / RBLK)        // 391 row blocks

// weight-buffer offsets (floats) inside g_wtf
#define WT_IN     0
#define WT_SRC(l) (8192 + (l) * 16384)
#define WT_DST(l) (57344 + (l) * 16384)
#define WT_TOT    106496

// ---------------- scratch (device globals; no runtime allocation) ----------------
__device__ float g_h  [(size_t)NN * HIDD];   // fp32 h (residual / LN / mean)
__device__ float g_htf[(size_t)NN * HIDD];   // tf32-valued copy of h (GEMM A input)
__device__ float g_fs [(size_t)NN * HIDD];
__device__ float g_fd [(size_t)NN * HIDD];
__device__ float g_wtf[WT_TOT];              // tf32-valued weights
__device__ int   g_csr_src[NE2];
__device__ int   g_rank[NE2];                // edge rank within its dst segment
__device__ int   g_rowptr [NN + 1];
__device__ int   g_cursor [NN];              // histogram counts
__device__ int   g_bsum[NB];

// ===================== tf32 rounding helper ======================================
__device__ __forceinline__ uint32_t f2tf(float x)   // round-to-nearest tf32
{
    uint32_t r;
    asm("cvt.rna.tf32.f32 %0, %1;" : "=r"(r) : "f"(x));
    return r;
}

// ================= weight pre-round (once per launch) ============================
__global__ void k_cvt_w(const float* __restrict__ W_in,
                        const float* __restrict__ W_src,
                        const float* __restrict__ W_dst)
{
    int i = blockIdx.x * blockDim.x + threadIdx.x;
    if (i >= WT_TOT) return;
    float v;
    if (i < 8192)        v = W_in[i];
    else if (i < 57344)  v = W_src[i - 8192];
    else                 v = W_dst[i - 57344];
    g_wtf[i] = __uint_as_float(f2tf(v));
}

// ================= CSR build (per launch; dst-only, layer-invariant) =============
__global__ void k_zero_cnt(float* __restrict__ out)
{
    int i = blockIdx.x * blockDim.x + threadIdx.x;
    if (i < NN) g_cursor[i] = 0;
    if (i < HIDD) out[i] = 0.f;               // zero graph-mean accumulator
}

// histogram; atomicAdd return value = rank of this edge within its dst segment
__global__ void k_hist(const int* __restrict__ dst)
{
    int e = blockIdx.x * blockDim.x + threadIdx.x;
    if (e >= NE2) return;
    int d = (e < EE) ? dst[e] : e - EE;
    g_rank[e] = atomicAdd(&g_cursor[d], 1);
}

__global__ void k_scan1()
{
    __shared__ int s[256];
    int t = threadIdx.x, i = blockIdx.x * 256 + t;
    int v = (i < NN) ? g_cursor[i] : 0;
    s[t] = v; __syncthreads();
    for (int o = 1; o < 256; o <<= 1) {
        int x = (t >= o) ? s[t - o] : 0;
        __syncthreads();
        s[t] += x;
        __syncthreads();
    }
    if (i < NN) g_rowptr[i] = s[t] - v;          // block-local exclusive
    if (t == 255) g_bsum[blockIdx.x] = s[255];
}

// scan3 with inlined block-offset reduction
__global__ void k_scan3()
{
    __shared__ int red[256];
    int t = threadIdx.x;
    int bid = blockIdx.x;
    int v = (t < NB && t < bid) ? g_bsum[t] : 0;
    red[t] = v; __syncthreads();
    #pragma unroll
    for (int o = 128; o; o >>= 1) {
        if (t < o) red[t] += red[t + o];
        __syncthreads();
    }
    int boff = red[0];
    int i = bid * 256 + t;
    if (i < NN) g_rowptr[i] += boff;
    if (i == 0) g_rowptr[NN] = NE2;
}

// atomic-free fill: pos = rowptr[d] + rank[e]
__global__ void k_fill(const int* __restrict__ src, const int* __restrict__ dst)
{
    int e = blockIdx.x * blockDim.x + threadIdx.x;
    if (e >= NE2) return;
    int s, d;
    if (e < EE) { s = src[e]; d = dst[e]; } else { s = e - EE; d = s; }
    g_csr_src[g_rowptr[d] + g_rank[e]] = s;
}

// ===================== tf32 tensor-core GEMM =====================================
__device__ __forceinline__ void mma_tf32(
    float& c0, float& c1, float& c2, float& c3,
    uint32_t a0, uint32_t a1, uint32_t a2, uint32_t a3,
    uint32_t b0, uint32_t b1)
{
    asm volatile(
        "mma.sync.aligned.m16n8k8.row.col.f32.tf32.tf32.f32 "
        "{%0,%1,%2,%3},{%4,%5,%6,%7},{%8,%9},{%0,%1,%2,%3};"
        : "+f"(c0), "+f"(c1), "+f"(c2), "+f"(c3)
        : "r"(a0), "r"(a1), "r"(a2), "r"(a3), "r"(b0), "r"(b1));
}

__device__ __forceinline__ void cp_async16(void* dst, const void* src, bool pred)
{
    uint32_t d = (uint32_t)__cvta_generic_to_shared(dst);
    int n = pred ? 16 : 0;
    asm volatile("cp.async.cg.shared.global [%0], [%1], 16, %2;"
                 :: "r"(d), "l"(src), "r"(n));
}
#define CP_COMMIT() asm volatile("cp.async.commit_group;")
#define CP_WAIT(N)  asm volatile("cp.async.wait_group %0;" :: "n"(N))

// smem layout (dynamic): As[2][128][36], Bs[2][32][132]
#define A_ST  (128 * 36)
#define B_ST  (32 * 132)
#define SMEM_BYTES ((2 * A_ST + 2 * B_ST) * 4)

// CVTA: convert A frags to tf32 at load (A not pre-rounded).
// TFOUT: also write tf32-rounded result to Ftf.
template<int KTOT, int AROW, bool CVTA, bool TFOUT>
__device__ __forceinline__ void gemm_tc_body(
    const float* __restrict__ A, const float* __restrict__ W,
    const float* __restrict__ bias, float* __restrict__ F,
    float* __restrict__ Ftf)
{
    extern __shared__ float sm[];
    float* AsB = sm;
    float* BsB = sm + 2 * A_ST;

    int tid = threadIdx.x;
    int lane = tid & 31, wid = tid >> 5;
    int wm = wid >> 2, wn = wid & 3;          // warp grid 2(m) x 4(n)
    int l4 = lane >> 2, lk = lane & 3;
    int row0 = blockIdx.x * RBLK;

    float c[4][4][4];
    #pragma unroll
    for (int i = 0; i < 4; i++)
        #pragma unroll
        for (int j = 0; j < 4; j++)
            #pragma unroll
            for (int q = 0; q < 4; q++) c[i][j][q] = 0.f;

    auto load_tiles = [&](int k0, int st) {
        float* As = AsB + st * A_ST;
        float* Bs = BsB + st * B_ST;
        #pragma unroll
        for (int i = 0; i < 4; i++) {
            int cix = tid + i * 256;
            int r = cix >> 3, cc = (cix & 7) * 4;
            int row = row0 + r;
            cp_async16(&As[r * 36 + cc], &A[(size_t)row * AROW + k0 + cc], row < NN);
        }
        #pragma unroll
        for (int i = 0; i < 4; i++) {
            int cix = tid + i * 256;
            int kk = cix >> 5, cc = (cix & 31) * 4;
            cp_async16(&Bs[kk * 132 + cc], &W[(size_t)(k0 + kk) * HIDD + cc], true);
        }
        CP_COMMIT();
    };

    auto afrag = [&](const float* As, int m, int k) -> uint32_t {
        return CVTA ? f2tf(As[m * 36 + k]) : __float_as_uint(As[m * 36 + k]);
    };

    const int NIT = KTOT / 32;
    load_tiles(0, 0);
    #pragma unroll
    for (int it = 0; it < NIT; it++) {
        int st = it & 1;
        if (it + 1 < NIT) { load_tiles((it + 1) * 32, st ^ 1); CP_WAIT(1); }
        else              { CP_WAIT(0); }
        __syncthreads();

        const float* As = AsB + st * A_ST;
        const float* Bs = BsB + st * B_ST;
        #pragma unroll
        for (int ks = 0; ks < 4; ks++) {
            int kc = ks * 8 + lk;
            uint32_t a[4][4], b[4][2];
            #pragma unroll
            for (int mf = 0; mf < 4; mf++) {
                int m0 = wm * 64 + mf * 16;
                a[mf][0] = afrag(As, m0 + l4,     kc    );
                a[mf][1] = afrag(As, m0 + l4 + 8, kc    );
                a[mf][2] = afrag(As, m0 + l4,     kc + 4);
                a[mf][3] = afrag(As, m0 + l4 + 8, kc + 4);
            }
            #pragma unroll
            for (int nf = 0; nf < 4; nf++) {
                int n0 = wn * 32 + nf * 8 + l4;
                b[nf][0] = __float_as_uint(Bs[(ks * 8 + lk    ) * 132 + n0]);
                b[nf][1] = __float_as_uint(Bs[(ks * 8 + lk + 4) * 132 + n0]);
            }
            #pragma unroll
            for (int mf = 0; mf < 4; mf++)
                #pragma unroll
                for (int nf = 0; nf < 4; nf++)
                    mma_tf32(c[mf][nf][0], c[mf][nf][1], c[mf][nf][2], c[mf][nf][3],
                             a[mf][0], a[mf][1], a[mf][2], a[mf][3],
                             b[nf][0], b[nf][1]);
        }
        __syncthreads();
    }

    // epilogue: bias + store (optionally also tf32-rounded copy)
    #pragma unroll
    for (int mf = 0; mf < 4; mf++) {
        int r = row0 + wm * 64 + mf * 16 + l4;
        #pragma unroll
        for (int nf = 0; nf < 4; nf++) {
            int col = wn * 32 + nf * 8 + lk * 2;
            float2 bb = *(const float2*)&bias[col];
            if (r < NN) {
                float2 o = { c[mf][nf][0] + bb.x, c[mf][nf][1] + bb.y };
                *(float2*)&F[(size_t)r * HIDD + col] = o;
                if (TFOUT) {
                    float2 ot = { __uint_as_float(f2tf(o.x)),
                                  __uint_as_float(f2tf(o.y)) };
                    *(float2*)&Ftf[(size_t)r * HIDD + col] = ot;
                }
            }
            if (r + 8 < NN) {
                float2 o = { c[mf][nf][2] + bb.x, c[mf][nf][3] + bb.y };
                *(float2*)&F[(size_t)(r + 8) * HIDD + col] = o;
                if (TFOUT) {
                    float2 ot = { __uint_as_float(f2tf(o.x)),
                                  __uint_as_float(f2tf(o.y)) };
                    *(float2*)&Ftf[(size_t)(r + 8) * HIDD + col] = ot;
                }
            }
        }
    }
}

__global__ __launch_bounds__(256) void k_gemm_in_tc(
    const float* __restrict__ A,     // [NN,64] node_feats (fp32, not pre-rounded)
    const float* __restrict__ bias)
{
    gemm_tc_body<64, 64, true, true>(A, g_wtf + WT_IN, bias, g_h, g_htf);
}

__global__ __launch_bounds__(256) void k_gemm_dual_tc(
    int l,
    const float* __restrict__ bs, const float* __restrict__ bd)
{
    if (blockIdx.y)
        gemm_tc_body<128, 128, false, false>(g_htf, g_wtf + WT_DST(l), bd, g_fd, nullptr);
    else
        gemm_tc_body<128, 128, false, false>(g_htf, g_wtf + WT_SRC(l), bs, g_fs, nullptr);
}

// ====== fused single-pass attention + aggregation + residual + LN + ReLU =========
// 2-edge unrolled: two independent gather/logit/exp chains interleaved for ILP.
__global__ __launch_bounds__(256) void k_agg_ln(
    const float* __restrict__ attn,   // [4*32] this layer
    const float* __restrict__ lng, const float* __restrict__ lnb,
    float* __restrict__ outh)         // last-layer copy target or null
{
    int n = (blockIdx.x * 256 + threadIdx.x) >> 5;
    int lane = threadIdx.x & 31;
    if (n >= NN) return;

    float4 fdv = *(const float4*)(g_fd + (size_t)n * HIDD + lane * 4);
    float4 wa  = *(const float4*)(attn + lane * 4);

    int beg = g_rowptr[n], end = g_rowptr[n + 1];

    float z = 0.f;
    float m0 = 0.f, m1 = 0.f, m2 = 0.f, m3 = 0.f;

    int i = beg;
    if ((end - beg) & 1) {
        int s = g_csr_src[i]; i++;
        float4 a = *(const float4*)(g_fs + (size_t)s * HIDD + lane * 4);
        float x0 = a.x + fdv.x; x0 = x0 > 0.f ? x0 : 0.2f * x0;
        float x1 = a.y + fdv.y; x1 = x1 > 0.f ? x1 : 0.2f * x1;
        float x2 = a.z + fdv.z; x2 = x2 > 0.f ? x2 : 0.2f * x2;
        float x3 = a.w + fdv.w; x3 = x3 > 0.f ? x3 : 0.2f * x3;
        float lg = x0 * wa.x + x1 * wa.y + x2 * wa.z + x3 * wa.w;
        lg += __shfl_xor_sync(0xffffffffu, lg, 4);
        lg += __shfl_xor_sync(0xffffffffu, lg, 2);
        lg += __shfl_xor_sync(0xffffffffu, lg, 1);
        float p = __expf(lg);
        z += p;
        m0 += p * a.x; m1 += p * a.y; m2 += p * a.z; m3 += p * a.w;
    }
    for (; i < end; i += 2) {
        int s0 = g_csr_src[i];
        int s1 = g_csr_src[i + 1];
        float4 a0 = *(const float4*)(g_fs + (size_t)s0 * HIDD + lane * 4);
        float4 a1 = *(const float4*)(g_fs + (size_t)s1 * HIDD + lane * 4);

        float u0 = a0.x + fdv.x; u0 = u0 > 0.f ? u0 : 0.2f * u0;
        float u1 = a0.y + fdv.y; u1 = u1 > 0.f ? u1 : 0.2f * u1;
        float u2 = a0.z + fdv.z; u2 = u2 > 0.f ? u2 : 0.2f * u2;
        float u3 = a0.w + fdv.w; u3 = u3 > 0.f ? u3 : 0.2f * u3;
        float v0 = a1.x + fdv.x; v0 = v0 > 0.f ? v0 : 0.2f * v0;
        float v1 = a1.y + fdv.y; v1 = v1 > 0.f ? v1 : 0.2f * v1;
        float v2 = a1.z + fdv.z; v2 = v2 > 0.f ? v2 : 0.2f * v2;
        float v3 = a1.w + fdv.w; v3 = v3 > 0.f ? v3 : 0.2f * v3;

        float lgA = u0 * wa.x + u1 * wa.y + u2 * wa.z + u3 * wa.w;
        float lgB = v0 * wa.x + v1 * wa.y + v2 * wa.z + v3 * wa.w;
        lgA += __shfl_xor_sync(0xffffffffu, lgA, 4);
        lgB += __shfl_xor_sync(0xffffffffu, lgB, 4);
        lgA += __shfl_xor_sync(0xffffffffu, lgA, 2);
        lgB += __shfl_xor_sync(0xffffffffu, lgB, 2);
        lgA += __shfl_xor_sync(0xffffffffu, lgA, 1);
        lgB += __shfl_xor_sync(0xffffffffu, lgB, 1);

        float pA = __expf(lgA);
        float pB = __expf(lgB);
        z += pA + pB;
        m0 += pA * a0.x + pB * a1.x;
        m1 += pA * a0.y + pB * a1.y;
        m2 += pA * a0.z + pB * a1.z;
        m3 += pA * a0.w + pB * a1.w;
    }
    float inv_z = 1.f / z;
    m0 *= inv_z; m1 *= inv_z; m2 *= inv_z; m3 *= inv_z;

    // residual + LN + ReLU
    size_t base = (size_t)n * HIDD + lane * 4;
    float4 hv = *(const float4*)(g_h + base);
    float x0 = 2.f * hv.x + m0;
    float x1 = 2.f * hv.y + m1;
    float x2 = 2.f * hv.z + m2;
    float x3 = 2.f * hv.w + m3;
    float su = x0 + x1 + x2 + x3;
    #pragma unroll
    for (int o = 16; o; o >>= 1) su += __shfl_xor_sync(0xffffffffu, su, o);
    float mu = su * (1.f / 128.f);
    float d0 = x0 - mu, d1 = x1 - mu, d2 = x2 - mu, d3 = x3 - mu;
    float sv = d0 * d0 + d1 * d1 + d2 * d2 + d3 * d3;
    #pragma unroll
    for (int o = 16; o; o >>= 1) sv += __shfl_xor_sync(0xffffffffu, sv, o);
    float inv = rsqrtf(sv * (1.f / 128.f) + 1e-5f);
    float4 gg = *(const float4*)(lng + lane * 4);
    float4 bb = *(const float4*)(lnb + lane * 4);
    float y0 = fmaxf(d0 * inv * gg.x + bb.x, 0.f);
    float y1 = fmaxf(d1 * inv * gg.y + bb.y, 0.f);
    float y2 = fmaxf(d2 * inv * gg.z + bb.z, 0.f);
    float y3 = fmaxf(d3 * inv * gg.w + bb.w, 0.f);
    float4 y = { y0, y1, y2, y3 };
    *(float4*)(g_h + base) = y;
    if (outh) {
        *(float4*)(outh + base) = y;          // last layer: no further GEMM
    } else {
        float4 yt = { __uint_as_float(f2tf(y0)), __uint_as_float(f2tf(y1)),
                      __uint_as_float(f2tf(y2)), __uint_as_float(f2tf(y3)) };
        *(float4*)(g_htf + base) = yt;        // feed next layer's GEMM raw
    }
}

// ---------------- graph mean ----------------
__global__ void k_mean(float* __restrict__ out)
{
    int c = threadIdx.x;              // 128 threads = feature
    int chunk = (NN + gridDim.x - 1) / gridDim.x;
    int n0 = blockIdx.x * chunk;
    int n1 = n0 + chunk; if (n1 > NN) n1 = NN;
    float s = 0.f;
    for (int n = n0; n < n1; n++) s += g_h[(size_t)n * HIDD + c];
    atomicAdd(&out[c], s * (1.f / (float)NN));
}

// ---------------- launch ----------------
extern "C" void kernel_launch(void* const* d_in, const int* in_sizes, int n_in,
                              void* d_out, int out_size)
{
    const float* nf    = (const float*)d_in[0];
    const int*   src   = (const int*)  d_in[1];
    const int*   dst   = (const int*)  d_in[2];
    const float* W_in  = (const float*)d_in[3];
    const float* b_in  = (const float*)d_in[4];
    const float* W_src = (const float*)d_in[5];
    const float* b_src = (const float*)d_in[6];
    const float* W_dst = (const float*)d_in[7];
    const float* b_dst = (const float*)d_in[8];
    const float* attn  = (const float*)d_in[9];
    const float* ln_g  = (const float*)d_in[10];
    const float* ln_b  = (const float*)d_in[11];
    float* out = (float*)d_out;

    (void)in_sizes; (void)n_in; (void)out_size;

    // lazily-created side stream + events (host-side resources only)
    static cudaStream_t s2 = nullptr;
    static cudaEvent_t evF, evCSR;
    if (!s2) {
        cudaStreamCreateWithFlags(&s2, cudaStreamNonBlocking);
        cudaEventCreateWithFlags(&evF,   cudaEventDisableTiming);
        cudaEventCreateWithFlags(&evCSR, cudaEventDisableTiming);
    }

    cudaFuncSetAttribute(k_gemm_in_tc,
        cudaFuncAttributeMaxDynamicSharedMemorySize, SMEM_BYTES);
    cudaFuncSetAttribute(k_gemm_dual_tc,
        cudaFuncAttributeMaxDynamicSharedMemorySize, SMEM_BYTES);

    const int gE = (NE2 + 255) / 256;
    const int gN = (NN + 255) / 256;
    const int gNodeWarp = (NN * 32 + 255) / 256;

    // ---- fork: CSR build on s2, overlapped with weight cvt + gemm_in + dual0 ----
    cudaEventRecord(evF, 0);
    cudaStreamWaitEvent(s2, evF, 0);
    k_zero_cnt<<<gN, 256, 0, s2>>>(out);
    k_hist<<<gE, 256, 0, s2>>>(dst);
    k_scan1<<<NB, 256, 0, s2>>>();
    k_scan3<<<gN, 256, 0, s2>>>();
    k_fill<<<gE, 256, 0, s2>>>(src, dst);
    cudaEventRecord(evCSR, s2);

    // ---- main stream: weight pre-round, input projection, layer-0 dual GEMM ----
    k_cvt_w<<<(WT_TOT + 255) / 256, 256>>>(W_in, W_src, W_dst);
    k_gemm_in_tc<<<NRB, 256, SMEM_BYTES>>>(nf, b_in);
    k_gemm_dual_tc<<<dim3(NRB, 2), 256, SMEM_BYTES>>>(0, b_src, b_dst);
    cudaStreamWaitEvent(0, evCSR, 0);          // CSR ready before first agg

    for (int l = 0; l < 3; l++) {
        k_agg_ln<<<gNodeWarp, 256>>>(
            attn + (size_t)l * HIDD,
            ln_g + (size_t)l * HIDD, ln_b + (size_t)l * HIDD,
            (l == 2) ? (out + HIDD) : nullptr);
        if (l < 2) {
            k_gemm_dual_tc<<<dim3(NRB, 2), 256, SMEM_BYTES>>>(
                l + 1, b_src + (size_t)(l + 1) * HIDD, b_dst + (size_t)(l + 1) * HIDD);
        }
    }

    k_mean<<<500, 128>>>(out);
}